// round 14
// baseline (speedup 1.0000x reference)
#include <cuda_runtime.h>
#include <cstdint>

#define SIZE   128
#define EPSF   1e-6f
#define BW     4            // half bandwidth of final operators
#define TAPS   9            // 2*BW+1
#define CW     12           // padded Lb coeff row width
#define SBW    5            // single-sweep inverse band half-width
#define HBW    12           // uniform band half-width for all stored matrices
#define BWID   25           // 2*HBW+1 storage width
#define NMAT   58           // 30 G + 15 H + 7 P/U + 3 T/V + 2 T2/N + 1 M

#define N_ID   56
#define M_ID   57

// ---------------------------------------------------------------------------
// Globals
// ---------------------------------------------------------------------------
__device__ float g_band[NMAT][SIZE * BWID];  // uniform banded storage
__device__ float g_Lb[SIZE * CW];            // row-major padded
__device__ float g_WbT[TAPS * SIZE];         // tap-major: WbT[d][j] = W[j-BW+d][j]

// product descriptor tables (tree):
// L1 (15): H_i = G_{2i+1} * G_{2i}              -> ids 30..44
// L2 (7):  P_p = H_{2p+1} * H_{2p} (p=0..4)     -> 45..49
//          U0 = H11*H10 -> 50, U1 = H13*H12 -> 51
// L3 (3):  T0 = P1*P0 -> 52, T1 = P3*P2 -> 53, V = U1*U0 -> 54
// L4 (2):  T2 = T1*T0 -> 55, N = H14*V -> 56
// L5 (1):  M  = P4*T2 -> 57
__device__ const int c_dst[28] = {30,31,32,33,34,35,36,37,38,39,40,41,42,43,44,
                                  45,46,47,48,49,50,51,
                                  52,53,54,
                                  55,56,
                                  57};
__device__ const int c_srA[28] = { 1, 3, 5, 7, 9,11,13,15,17,19,21,23,25,27,29,
                                  31,33,35,37,39,41,43,
                                  46,48,51,
                                  53,44,
                                  49};
__device__ const int c_srB[28] = { 0, 2, 4, 6, 8,10,12,14,16,18,20,22,24,26,28,
                                  30,32,34,36,38,40,42,
                                  45,47,50,
                                  52,54,
                                  55};

// ---------------------------------------------------------------------------
// sweep_inv: grid 150 (redundant CTAs). Closed-form banded inverse per solve:
//   (M^-1)_{ij} = (Π co) θ_{i-1} φ_{j+1} / θ_{n-1},  stored as 25-wide band.
// X sweeps s=0..19 (m0=s: k=m0>>1, t=(k+(m0&1))*DT, dt=DT/2);
// Y sweeps s=20..29 (m0=s-20: t=m0*DT+DT/2, dt=DT).
// ---------------------------------------------------------------------------
__global__ void __launch_bounds__(128, 1)
sweep_inv_kernel(const float* __restrict__ abx, const float* __restrict__ atx,
                 const float* __restrict__ aqx, const float* __restrict__ bby,
                 const float* __restrict__ bty, const float* __restrict__ bqy)
{
    __shared__ float co[SIZE];
    __shared__ float th[SIZE + 1];
    __shared__ float ph[SIZE + 1];

    const int s  = blockIdx.x % 30;
    const bool isY = s >= 20;
    const int m0 = isY ? s - 20 : s;
    const int i  = threadIdx.x;

    float t, dt; const float *bp, *lp, *qp;
    if (isY) { t = m0 * 0.01f + 0.005f;                     dt = 0.01f;  bp = bby; lp = bty; qp = bqy; }
    else     { int k = m0 >> 1; t = (k + (m0 & 1)) * 0.01f; dt = 0.005f; bp = abx; lp = atx; qp = aqx; }

    int im = max(i - 1, 0), ip = min(i + 1, 127);
    float vm = fmaxf(bp[im] + lp[im] * t + qp[im] * t * t, EPSF);
    float vc = fmaxf(bp[i]  + lp[i]  * t + qp[i]  * t * t, EPSF);
    float vp = fmaxf(bp[ip] + lp[ip] * t + qp[ip] * t * t, EPSF);
    co[i] = (vm + vc + vp) * (1.0f / 3.0f) * dt;
    __syncthreads();

    if (i == 0) {
        float t2 = 1.0f;
        float cprev = co[0];
        float t1 = 1.0f + cprev;
        th[0] = 1.0f; th[1] = t1;
        for (int r = 1; r < SIZE; r++) {
            float cr = co[r];
            float br = (r == SIZE - 1) ? (1.0f + cr) : (1.0f + 2.0f * cr);
            float tn = br * t1 - (cr * cprev) * t2;
            th[r + 1] = tn;
            t2 = t1; t1 = tn; cprev = cr;
        }
    } else if (i == 64) {
        float p2 = 1.0f;
        float cnext = co[SIZE - 1];
        float p1 = 1.0f + cnext;
        ph[SIZE] = 1.0f; ph[SIZE - 1] = p1;
        for (int r = SIZE - 2; r >= 0; r--) {
            float cr = co[r];
            float br = (r == 0) ? (1.0f + cr) : (1.0f + 2.0f * cr);
            float pn = br * p1 - (cr * cnext) * p2;
            ph[r] = pn;
            p2 = p1; p1 = pn; cnext = cr;
        }
    }
    __syncthreads();

    const float invthn = 1.0f / th[SIZE];
    #pragma unroll 1
    for (int e = 0; e < BWID; e++) {
        int j = i - HBW + e;
        float g = 0.0f;
        if (j >= 0 && j < SIZE && j - i >= -SBW && j - i <= SBW) {
            float prod = 1.0f;
            if (i <= j) {
                for (int k = i; k < j; k++) prod *= co[k];
                g = prod * th[i] * ph[j + 1] * invthn;
            } else {
                for (int k = j + 1; k <= i; k++) prod *= co[k];
                g = prod * th[j] * ph[i + 1] * invthn;
            }
        }
        g_band[s][i * BWID + e] = g;
    }
}

// ---------------------------------------------------------------------------
// bmul: one tree level per launch. CTA (mod nprod) -> one product D = A * B,
// entry-parallel over 128x25 band entries. When D is N or M, also emit the
// final Lb / WbT tables (band of the full chain operator).
// ---------------------------------------------------------------------------
__global__ void __launch_bounds__(1024, 1)
bmul_kernel(int off, int nprod)
{
    const int prod = off + (int)(blockIdx.x % (unsigned)nprod);
    const int dst = c_dst[prod];
    const float* __restrict__ A = g_band[c_srA[prod]];
    const float* __restrict__ B = g_band[c_srB[prod]];
    float* __restrict__ D = g_band[dst];

    #pragma unroll 1
    for (int e = threadIdx.x; e < SIZE * BWID; e += 1024) {
        int r = e / BWID, o = e - r * BWID;
        int c = r - HBW + o;
        float s = 0.0f;
        if (c >= 0 && c < SIZE) {
            int klo = max(max(r, c) - HBW, 0);
            int khi = min(min(r, c) + HBW, SIZE - 1);
            const float* ap = A + r * BWID + (klo - r + HBW);
            const float* bp = B + klo * BWID + (c - klo + HBW);
            for (int k = klo; k <= khi; k++) {
                s += (*ap) * (*bp);
                ap += 1;
                bp += (BWID - 1);
            }
        }
        D[e] = s;

        if (dst == N_ID) {             // Lb[r][d] = N[r][r-4+d], d<TAPS; pad to CW
            if (o >= HBW - BW && o <= HBW + BW)
                g_Lb[r * CW + (o - (HBW - BW))] = s;
            else if (o > HBW + BW && o <= HBW + BW + (CW - TAPS))
                g_Lb[r * CW + (o - (HBW - BW))] = 0.0f;
        } else if (dst == M_ID) {      // WbT[d][j] = M[j][j-4+d]
            if (o >= HBW - BW && o <= HBW + BW)
                g_WbT[(o - (HBW - BW)) * SIZE + r] = s;
        }
    }
}

// ---------------------------------------------------------------------------
// band_kernel (R12/R13 verbatim — measured 52.9us): ONE CTA per image,
// 256 threads, 8 warps x 16 rows, 2 CTAs/SM. Register sliding window
// (9 float4), Lb warp-uniform LDG, Wb in 36 regs (tap-major).
// ---------------------------------------------------------------------------
__device__ __forceinline__ float4 f4fma(float c, float4 w, float4 a) {
    a.x = fmaf(c, w.x, a.x); a.y = fmaf(c, w.y, a.y);
    a.z = fmaf(c, w.z, a.z); a.w = fmaf(c, w.w, a.w);
    return a;
}

__global__ void __launch_bounds__(256, 2)
band_kernel(const float* __restrict__ uin, float* __restrict__ uout)
{
    extern __shared__ float us[];            // 128*128 floats = 64KB

    const int tid  = threadIdx.x, w = tid >> 5, lane = tid & 31;
    const size_t off = (size_t)blockIdx.x * (SIZE * SIZE);
    const float* src = uin + off;

    const float4* src4 = (const float4*)src;
    #pragma unroll
    for (int q = 0; q < 16; q++) {
        int m = tid + q * 256;
        int r = m >> 5, c4 = (m & 31) * 4;
        *(float4*)&us[r * SIZE + c4] = src4[m];
    }

    float4 wb4[TAPS];
    #pragma unroll
    for (int d = 0; d < TAPS; d++)
        wb4[d] = *(const float4*)&g_WbT[d * SIZE + 4 * lane];
    __syncthreads();

    const int il0 = w * 16;
    float4 win[TAPS];
    #pragma unroll
    for (int t = 0; t < TAPS - 1; t++) {
        int r = max(il0 - BW + t, 0);        // clamp: edge coeffs are zero
        win[t] = *(const float4*)&us[r * SIZE + 4 * lane];
    }

    float* dst = uout + off;
    #pragma unroll
    for (int rr = 0; rr < 16; rr++) {
        int rn = min(il0 + rr + BW, SIZE - 1);
        win[(rr + TAPS - 1) % TAPS] = *(const float4*)&us[rn * SIZE + 4 * lane];
        const int gi = il0 + rr;

        const float* cr = &g_Lb[gi * CW];
        float4 c0 = *(const float4*)cr;
        float4 c1 = *(const float4*)(cr + 4);
        float  c8 = cr[8];
        float4 t4 = make_float4(0.f, 0.f, 0.f, 0.f);
        t4 = f4fma(c0.x, win[(rr + 0) % TAPS], t4);
        t4 = f4fma(c0.y, win[(rr + 1) % TAPS], t4);
        t4 = f4fma(c0.z, win[(rr + 2) % TAPS], t4);
        t4 = f4fma(c0.w, win[(rr + 3) % TAPS], t4);
        t4 = f4fma(c1.x, win[(rr + 4) % TAPS], t4);
        t4 = f4fma(c1.y, win[(rr + 5) % TAPS], t4);
        t4 = f4fma(c1.z, win[(rr + 6) % TAPS], t4);
        t4 = f4fma(c1.w, win[(rr + 7) % TAPS], t4);
        t4 = f4fma(c8,   win[(rr + 8) % TAPS], t4);

        float Tl[12];
        Tl[0] = __shfl_up_sync(0xffffffffu, t4.x, 1);
        Tl[1] = __shfl_up_sync(0xffffffffu, t4.y, 1);
        Tl[2] = __shfl_up_sync(0xffffffffu, t4.z, 1);
        Tl[3] = __shfl_up_sync(0xffffffffu, t4.w, 1);
        Tl[4] = t4.x; Tl[5] = t4.y; Tl[6] = t4.z; Tl[7] = t4.w;
        Tl[8]  = __shfl_down_sync(0xffffffffu, t4.x, 1);
        Tl[9]  = __shfl_down_sync(0xffffffffu, t4.y, 1);
        Tl[10] = __shfl_down_sync(0xffffffffu, t4.z, 1);
        Tl[11] = __shfl_down_sync(0xffffffffu, t4.w, 1);

        float4 o = make_float4(0.f, 0.f, 0.f, 0.f);
        #pragma unroll
        for (int d = 0; d < TAPS; d++) {
            o.x = fmaf(wb4[d].x, Tl[0 + d], o.x);
            o.y = fmaf(wb4[d].y, Tl[1 + d], o.y);
            o.z = fmaf(wb4[d].z, Tl[2 + d], o.z);
            o.w = fmaf(wb4[d].w, Tl[3 + d], o.w);
        }
        *(float4*)&dst[gi * SIZE + 4 * lane] = o;
    }
}

// ---------------------------------------------------------------------------
extern "C" void kernel_launch(void* const* d_in, const int* in_sizes, int n_in,
                              void* d_out, int out_size)
{
    const float* u   = (const float*)d_in[0];
    const float* abx = (const float*)d_in[1];
    const float* bby = (const float*)d_in[4];
    const float* atx = (const float*)d_in[5];
    const float* bty = (const float*)d_in[8];
    const float* aqx = (const float*)d_in[9];
    const float* bqy = (const float*)d_in[12];
    float* out = (float*)d_out;

    const int smem_band = SIZE * SIZE * (int)sizeof(float);   // 65536
    cudaFuncSetAttribute(band_kernel, cudaFuncAttributeMaxDynamicSharedMemorySize, smem_band);

    const int batch = out_size / (SIZE * SIZE);   // 2048

    sweep_inv_kernel<<<150, 128>>>(abx, atx, aqx, bby, bty, bqy);
    bmul_kernel<<<150, 1024>>>( 0, 15);   // level 1: 15 pair products (H)
    bmul_kernel<<<154, 1024>>>(15,  7);   // level 2: P0..P4, U0, U1
    bmul_kernel<<<150, 1024>>>(22,  3);   // level 3: T0, T1, V
    bmul_kernel<<<148, 1024>>>(25,  2);   // level 4: T2, N (-> g_Lb)
    bmul_kernel<<<148, 1024>>>(27,  1);   // level 5: M (-> g_WbT)
    band_kernel<<<batch, 256, smem_band>>>(u, out);
}

// round 15
// speedup vs baseline: 1.3548x; 1.3548x over previous
#include <cuda_runtime.h>
#include <cstdint>

#define SIZE   128
#define EPSF   1e-6f
#define BW     4            // final operator half bandwidth
#define TAPS   9            // 2*BW+1
#define CW     12           // padded Lb coeff row width
#define SBW    5            // single-sweep inverse half-width
#define GW     11           // 2*SBW+1
#define HA1    10           // A1/A2 half-width (exact)
#define WA1    21
#define HC     12           // chain / E half-width (cap, validated)
#define WC     25

// ---------------------------------------------------------------------------
// Globals
// ---------------------------------------------------------------------------
// chains 0..3 = X chains (W = C0*C1*C2*C3), 4..5 = Y chains (L = C5*C4)
__device__ float g_cb[6][SIZE * WC];
__device__ float g_Lb[SIZE * CW];          // row-major padded
__device__ float g_WbT[TAPS * SIZE];       // tap-major: WbT[d][j] = W[j-BW+d][j]

// ---------------------------------------------------------------------------
// banded product (smem): D[r][c] = sum_k A[r][k] * B[k][c], band widths ha/hb/hd
// ---------------------------------------------------------------------------
__device__ __forceinline__ void bprod(const float* __restrict__ A, int ha,
                                      const float* __restrict__ B, int hb,
                                      float* __restrict__ D, int hd,
                                      int tid, int nthr)
{
    const int wa = 2 * ha + 1, wb = 2 * hb + 1, wd = 2 * hd + 1;
    for (int e = tid; e < SIZE * wd; e += nthr) {
        int r = e / wd, o = e - r * wd;
        int c = r - hd + o;
        float s = 0.0f;
        if (c >= 0 && c < SIZE) {
            int klo = max(max(r - ha, c - hb), 0);
            int khi = min(min(r + ha, c + hb), SIZE - 1);
            for (int k = klo; k <= khi; k++)
                s += A[r * wa + (k - r + ha)] * B[k * wb + (c - k + hb)];
        }
        D[e] = s;
    }
}

// closed-form tridiagonal inverse entry (validated R11):
__device__ __forceinline__ float ginv(const float* co, const float* th,
                                      const float* ph, float invthn, int i, int j)
{
    float prod = 1.0f;
    if (i <= j) {
        for (int k = i; k < j; k++) prod *= co[k];
        return prod * th[i] * ph[j + 1] * invthn;
    } else {
        for (int k = j + 1; k <= i; k++) prod *= co[k];
        return prod * th[j] * ph[i + 1] * invthn;
    }
}

// ---------------------------------------------------------------------------
// K1: one CTA (mod 6) builds one complete 5-sweep chain band in smem.
// parts 0..3: X chains (store G^T; C = G0^T G1^T G2^T G3^T G4^T)
// parts 4..5: Y chains (store G;   C = G4 G3 G2 G1 G0)
// X chain p: X-order sweeps m=5p+q (k=m>>1, t=(k+(m&1))*DT, dt=DT/2)
// Y chain p: Y-order sweeps m=5(p-4)+q (t=m*DT+DT/2, dt=DT)
// ---------------------------------------------------------------------------
#define K1_CO   0
#define K1_TH   (K1_CO + 5 * SIZE)          // th[q*130+i] = theta_{i-1}
#define K1_PH   (K1_TH + 5 * 130)
#define K1_IV   (K1_PH + 5 * 130)           // 8 (5 used)
#define K1_G    (K1_IV + 8)                 // 5 * 128 * GW
#define K1_A1   (K1_G + 5 * SIZE * GW)      // 128*21
#define K1_A2   (K1_A1 + SIZE * WA1)
#define K1_A3   (K1_A2 + SIZE * WA1)        // 128*25
#define K1_C    (K1_A3 + SIZE * WC)
#define K1_TOT  (K1_C + SIZE * WC)

__global__ void __launch_bounds__(1024, 1)
chain_kernel(const float* __restrict__ abx, const float* __restrict__ atx,
             const float* __restrict__ aqx, const float* __restrict__ bby,
             const float* __restrict__ bty, const float* __restrict__ bqy)
{
    extern __shared__ float sh[];
    float* co  = sh + K1_CO;
    float* th  = sh + K1_TH;
    float* ph  = sh + K1_PH;
    float* ivt = sh + K1_IV;
    float* gbs = sh + K1_G;
    float* A1  = sh + K1_A1;
    float* A2  = sh + K1_A2;
    float* A3  = sh + K1_A3;
    float* C   = sh + K1_C;

    const int tid  = threadIdx.x;
    const int part = blockIdx.x % 6;
    const bool isY = part >= 4;

    // ---- coefficients (5 sweeps x 128, parallel) ----
    for (int e = tid; e < 5 * SIZE; e += 1024) {
        int q = e >> 7, i = e & 127;
        int m = isY ? (part - 4) * 5 + q : part * 5 + q;
        float t, dt; const float *bp, *lp, *qp;
        if (isY) { t = m * 0.01f + 0.005f;                   dt = 0.01f;  bp = bby; lp = bty; qp = bqy; }
        else     { int k = m >> 1; t = (k + (m & 1)) * 0.01f; dt = 0.005f; bp = abx; lp = atx; qp = aqx; }
        int im = max(i - 1, 0), ip = min(i + 1, 127);
        float vm = fmaxf(bp[im] + lp[im] * t + qp[im] * t * t, EPSF);
        float vc = fmaxf(bp[i]  + lp[i]  * t + qp[i]  * t * t, EPSF);
        float vp = fmaxf(bp[ip] + lp[ip] * t + qp[ip] * t * t, EPSF);
        co[q * SIZE + i] = (vm + vc + vp) * (1.0f / 3.0f) * dt;
    }
    __syncthreads();

    // ---- theta (warp0 lanes 0..4) / phi (warp1 lanes 0..4) ----
    if (tid < 5) {
        const int q = tid;
        const float* c = &co[q * SIZE];
        float t2 = 1.0f, cprev = c[0];
        float t1 = 1.0f + cprev;
        th[q * 130 + 0] = 1.0f; th[q * 130 + 1] = t1;
        for (int r = 1; r < SIZE; r++) {
            float cr = c[r];
            float br = (r == SIZE - 1) ? (1.0f + cr) : (1.0f + 2.0f * cr);
            float tn = br * t1 - (cr * cprev) * t2;
            th[q * 130 + r + 1] = tn;
            t2 = t1; t1 = tn; cprev = cr;
        }
        ivt[q] = 1.0f / th[q * 130 + SIZE];
    } else if (tid >= 32 && tid < 37) {
        const int q = tid - 32;
        const float* c = &co[q * SIZE];
        float p2 = 1.0f, cnext = c[SIZE - 1];
        float p1 = 1.0f + cnext;
        ph[q * 130 + SIZE] = 1.0f; ph[q * 130 + SIZE - 1] = p1;
        for (int r = SIZE - 2; r >= 0; r--) {
            float cr = c[r];
            float br = (r == 0) ? (1.0f + cr) : (1.0f + 2.0f * cr);
            float pn = br * p1 - (cr * cnext) * p2;
            ph[q * 130 + r] = pn;
            p2 = p1; p1 = pn; cnext = cr;
        }
    }
    __syncthreads();

    // ---- G bands (hw 5). X parts store G^T (swap args) ----
    for (int e = tid; e < 5 * SIZE * GW; e += 1024) {
        int q = e / (SIZE * GW);
        int rem = e - q * (SIZE * GW);
        int r = rem / GW, o = rem - r * GW;
        int c = r - SBW + o;
        float v = 0.0f;
        if (c >= 0 && c < SIZE) {
            const float* cq = &co[q * SIZE];
            const float* tq = &th[q * 130];
            const float* pq = &ph[q * 130];
            v = isY ? ginv(cq, tq, pq, ivt[q], r, c)
                    : ginv(cq, tq, pq, ivt[q], c, r);
        }
        gbs[e] = v;
    }
    __syncthreads();

    // ---- product tree in smem ----
    const float* g0 = gbs + (isY ? 4 : 0) * SIZE * GW;
    const float* g1 = gbs + (isY ? 3 : 1) * SIZE * GW;
    const float* g2 = gbs + 2 * SIZE * GW;
    const float* g3 = gbs + (isY ? 1 : 3) * SIZE * GW;
    const float* g4 = gbs + (isY ? 0 : 4) * SIZE * GW;

    bprod(g0, SBW, g1, SBW, A1, HA1, tid, 1024);
    bprod(g2, SBW, g3, SBW, A2, HA1, tid, 1024);
    __syncthreads();
    bprod(A1, HA1, A2, HA1, A3, HC, tid, 1024);
    __syncthreads();
    bprod(A3, HC, g4, SBW, C, HC, tid, 1024);
    __syncthreads();

    for (int e = tid; e < SIZE * WC; e += 1024)
        g_cb[part][e] = C[e];
}

// ---------------------------------------------------------------------------
// K2: finalize band tables. CTA (mod 2):
// role 0: E1=C0*C1, E2=C2*C3 (hw 12), then WbT[d][j] = (E1*E2)[j-4+d][j]
// role 1: Lb[i][d] = (C5*C4)[i][i-4+d]
// ---------------------------------------------------------------------------
__global__ void __launch_bounds__(1024, 1)
finalize_kernel()
{
    extern __shared__ float sh[];
    float* cs = sh;                     // up to 4 * 3200
    float* E  = sh + 4 * SIZE * WC;     // 2 * 3200
    const int tid  = threadIdx.x;
    const int role = blockIdx.x % 2;

    if (role == 0) {
        for (int m = tid; m < 4 * SIZE * WC; m += 1024)
            cs[m] = ((const float*)g_cb)[m];                 // C0..C3
        __syncthreads();

        // E1 = C0*C1, E2 = C2*C3
        for (int e = tid; e < 2 * SIZE * WC; e += 1024) {
            int which = e / (SIZE * WC);
            int rem = e - which * (SIZE * WC);
            int r = rem / WC, o = rem - r * WC;
            int c = r - HC + o;
            float s = 0.0f;
            if (c >= 0 && c < SIZE) {
                const float* A = cs + (2 * which)     * SIZE * WC;
                const float* B = cs + (2 * which + 1) * SIZE * WC;
                int klo = max(max(r, c) - HC, 0), khi = min(min(r, c) + HC, SIZE - 1);
                for (int k = klo; k <= khi; k++)
                    s += A[r * WC + (k - r + HC)] * B[k * WC + (c - k + HC)];
            }
            E[e] = s;
        }
        __syncthreads();

        // WbT[d][j] = (E1*E2)[j-4+d][j]
        const float* E1 = E, *E2 = E + SIZE * WC;
        for (int e = tid; e < TAPS * SIZE; e += 1024) {
            int d = e / SIZE, j = e - d * SIZE;
            int r = j - BW + d;
            float s = 0.0f;
            if (r >= 0 && r < SIZE) {
                int klo = max(max(r, j) - HC, 0), khi = min(min(r, j) + HC, SIZE - 1);
                for (int k = klo; k <= khi; k++)
                    s += E1[r * WC + (k - r + HC)] * E2[k * WC + (j - k + HC)];
            }
            g_WbT[e] = s;
        }
    } else {
        for (int m = tid; m < 2 * SIZE * WC; m += 1024)
            cs[m] = ((const float*)g_cb)[4 * SIZE * WC + m]; // C4, C5
        __syncthreads();

        const float* C4 = cs, *C5 = cs + SIZE * WC;
        for (int e = tid; e < SIZE * TAPS; e += 1024) {
            int i = e / TAPS, d = e - i * TAPS;
            int c = i - BW + d;
            float s = 0.0f;
            if (c >= 0 && c < SIZE) {
                int klo = max(max(i, c) - HC, 0), khi = min(min(i, c) + HC, SIZE - 1);
                for (int k = klo; k <= khi; k++)
                    s += C5[i * WC + (k - i + HC)] * C4[k * WC + (c - k + HC)];
            }
            g_Lb[i * CW + d] = s;
        }
    }
}

// ---------------------------------------------------------------------------
// band_kernel (R12/R13 verbatim — measured 52.9us): ONE CTA per image,
// 256 threads, 8 warps x 16 rows, 2 CTAs/SM. Register sliding window
// (9 float4), Lb warp-uniform LDG, Wb in 36 regs (tap-major).
// ---------------------------------------------------------------------------
__device__ __forceinline__ float4 f4fma(float c, float4 w, float4 a) {
    a.x = fmaf(c, w.x, a.x); a.y = fmaf(c, w.y, a.y);
    a.z = fmaf(c, w.z, a.z); a.w = fmaf(c, w.w, a.w);
    return a;
}

__global__ void __launch_bounds__(256, 2)
band_kernel(const float* __restrict__ uin, float* __restrict__ uout)
{
    extern __shared__ float us[];            // 128*128 floats = 64KB

    const int tid  = threadIdx.x, w = tid >> 5, lane = tid & 31;
    const size_t off = (size_t)blockIdx.x * (SIZE * SIZE);
    const float* src = uin + off;

    const float4* src4 = (const float4*)src;
    #pragma unroll
    for (int q = 0; q < 16; q++) {
        int m = tid + q * 256;
        int r = m >> 5, c4 = (m & 31) * 4;
        *(float4*)&us[r * SIZE + c4] = src4[m];
    }

    float4 wb4[TAPS];
    #pragma unroll
    for (int d = 0; d < TAPS; d++)
        wb4[d] = *(const float4*)&g_WbT[d * SIZE + 4 * lane];
    __syncthreads();

    const int il0 = w * 16;
    float4 win[TAPS];
    #pragma unroll
    for (int t = 0; t < TAPS - 1; t++) {
        int r = max(il0 - BW + t, 0);        // clamp: edge coeffs are zero
        win[t] = *(const float4*)&us[r * SIZE + 4 * lane];
    }

    float* dst = uout + off;
    #pragma unroll
    for (int rr = 0; rr < 16; rr++) {
        int rn = min(il0 + rr + BW, SIZE - 1);
        win[(rr + TAPS - 1) % TAPS] = *(const float4*)&us[rn * SIZE + 4 * lane];
        const int gi = il0 + rr;

        const float* cr = &g_Lb[gi * CW];
        float4 c0 = *(const float4*)cr;
        float4 c1 = *(const float4*)(cr + 4);
        float  c8 = cr[8];
        float4 t4 = make_float4(0.f, 0.f, 0.f, 0.f);
        t4 = f4fma(c0.x, win[(rr + 0) % TAPS], t4);
        t4 = f4fma(c0.y, win[(rr + 1) % TAPS], t4);
        t4 = f4fma(c0.z, win[(rr + 2) % TAPS], t4);
        t4 = f4fma(c0.w, win[(rr + 3) % TAPS], t4);
        t4 = f4fma(c1.x, win[(rr + 4) % TAPS], t4);
        t4 = f4fma(c1.y, win[(rr + 5) % TAPS], t4);
        t4 = f4fma(c1.z, win[(rr + 6) % TAPS], t4);
        t4 = f4fma(c1.w, win[(rr + 7) % TAPS], t4);
        t4 = f4fma(c8,   win[(rr + 8) % TAPS], t4);

        float Tl[12];
        Tl[0] = __shfl_up_sync(0xffffffffu, t4.x, 1);
        Tl[1] = __shfl_up_sync(0xffffffffu, t4.y, 1);
        Tl[2] = __shfl_up_sync(0xffffffffu, t4.z, 1);
        Tl[3] = __shfl_up_sync(0xffffffffu, t4.w, 1);
        Tl[4] = t4.x; Tl[5] = t4.y; Tl[6] = t4.z; Tl[7] = t4.w;
        Tl[8]  = __shfl_down_sync(0xffffffffu, t4.x, 1);
        Tl[9]  = __shfl_down_sync(0xffffffffu, t4.y, 1);
        Tl[10] = __shfl_down_sync(0xffffffffu, t4.z, 1);
        Tl[11] = __shfl_down_sync(0xffffffffu, t4.w, 1);

        float4 o = make_float4(0.f, 0.f, 0.f, 0.f);
        #pragma unroll
        for (int d = 0; d < TAPS; d++) {
            o.x = fmaf(wb4[d].x, Tl[0 + d], o.x);
            o.y = fmaf(wb4[d].y, Tl[1 + d], o.y);
            o.z = fmaf(wb4[d].z, Tl[2 + d], o.z);
            o.w = fmaf(wb4[d].w, Tl[3 + d], o.w);
        }
        *(float4*)&dst[gi * SIZE + 4 * lane] = o;
    }
}

// ---------------------------------------------------------------------------
extern "C" void kernel_launch(void* const* d_in, const int* in_sizes, int n_in,
                              void* d_out, int out_size)
{
    const float* u   = (const float*)d_in[0];
    const float* abx = (const float*)d_in[1];
    const float* bby = (const float*)d_in[4];
    const float* atx = (const float*)d_in[5];
    const float* bty = (const float*)d_in[8];
    const float* aqx = (const float*)d_in[9];
    const float* bqy = (const float*)d_in[12];
    float* out = (float*)d_out;

    const int smem_k1   = K1_TOT * (int)sizeof(float);            // ~83 KB
    const int smem_k2   = 6 * SIZE * WC * (int)sizeof(float);     // 76.8 KB
    const int smem_band = SIZE * SIZE * (int)sizeof(float);       // 65536

    cudaFuncSetAttribute(chain_kernel,    cudaFuncAttributeMaxDynamicSharedMemorySize, smem_k1);
    cudaFuncSetAttribute(finalize_kernel, cudaFuncAttributeMaxDynamicSharedMemorySize, smem_k2);
    cudaFuncSetAttribute(band_kernel,     cudaFuncAttributeMaxDynamicSharedMemorySize, smem_band);

    const int batch = out_size / (SIZE * SIZE);   // 2048

    chain_kernel<<<150, 1024, smem_k1>>>(abx, atx, aqx, bby, bty, bqy);
    finalize_kernel<<<148, 1024, smem_k2>>>();
    band_kernel<<<batch, 256, smem_band>>>(u, out);
}